// round 14
// baseline (speedup 1.0000x reference)
#include <cuda_runtime.h>
#include <cuda_fp16.h>
#include <cstdint>

// ---------------------------------------------------------------------------
// x[65536,512] -> qkv = x @ qkv_w^T -> windowed attn (1024x8, 64x64x64)
//   -> out = att @ proj_w^T + b
// GEMMs: HMMA fp16 2-term split C = (Ah+Al)*Bh, BK=64 DOUBLE-buffered
// cp.async pipeline. QKV GEMM emits fp16 hi/lo directly; attention consumes
// hi/lo via cp.async (no conversion in attn).
// ---------------------------------------------------------------------------

#define M_ROWS   65536
#define C_DIM    512
#define QKV_DIM  1536
#define NH       8
#define HD       64
#define WINW     64
#define NWIN     1024

__device__ __half g_qkvh[(long long)M_ROWS * QKV_DIM];  // qkv hi (fp16)
__device__ __half g_qkvl[(long long)M_ROWS * QKV_DIM];  // qkv lo (fp16)
__device__ __half g_xh [(long long)M_ROWS * C_DIM];
__device__ __half g_xl [(long long)M_ROWS * C_DIM];
__device__ __half g_ath[(long long)M_ROWS * C_DIM];
__device__ __half g_atl[(long long)M_ROWS * C_DIM];
__device__ __half g_wqh[QKV_DIM * C_DIM];
__device__ __half g_wql[QKV_DIM * C_DIM];
__device__ __half g_wph[C_DIM * C_DIM];
__device__ __half g_wpl[C_DIM * C_DIM];

// ------------------------------ helpers ------------------------------------
__device__ __forceinline__ uint32_t smem_u32(const void* p) {
    uint32_t a;
    asm("{ .reg .u64 t; cvta.to.shared.u64 t, %1; cvt.u32.u64 %0, t; }"
        : "=r"(a) : "l"(p));
    return a;
}
__device__ __forceinline__ void ldsm4(uint32_t addr, uint32_t r[4]) {
    asm volatile("ldmatrix.sync.aligned.m8n8.x4.shared.b16 {%0,%1,%2,%3}, [%4];"
                 : "=r"(r[0]), "=r"(r[1]), "=r"(r[2]), "=r"(r[3]) : "r"(addr));
}
__device__ __forceinline__ void mma16816(float d[4], const uint32_t a[4],
                                         const uint32_t b0, const uint32_t b1) {
    asm volatile(
        "mma.sync.aligned.m16n8k16.row.col.f32.f16.f16.f32 "
        "{%0,%1,%2,%3},{%4,%5,%6,%7},{%8,%9},{%0,%1,%2,%3};"
        : "+f"(d[0]), "+f"(d[1]), "+f"(d[2]), "+f"(d[3])
        : "r"(a[0]), "r"(a[1]), "r"(a[2]), "r"(a[3]), "r"(b0), "r"(b1));
}
__device__ __forceinline__ void cp16(uint32_t saddr, const void* gaddr) {
    asm volatile("cp.async.cg.shared.global [%0], [%1], 16;"
                 :: "r"(saddr), "l"(gaddr));
}
#define CP_COMMIT() asm volatile("cp.async.commit_group;" ::: "memory")
#define CP_WAIT(n)  asm volatile("cp.async.wait_group %0;" :: "n"(n) : "memory")

__device__ __forceinline__ uint32_t pack2(__half a, __half b) {
    return ((uint32_t)__half_as_ushort(b) << 16) | __half_as_ushort(a);
}
__device__ __forceinline__ void split1(float v, __half& h, __half& l) {
    h = __float2half_rn(v);
    l = __float2half_rn(v - __half2float(h));
}
__device__ __forceinline__ void split_pack(float x, float y,
                                           uint32_t& hh, uint32_t& ll) {
    __half h0, l0, h1, l1;
    split1(x, h0, l0);
    split1(y, h1, l1);
    hh = pack2(h0, h1);
    ll = pack2(l0, l1);
}

// Fast e^x on the FMA pipe (x <= 0). |err| ~ 1e-7 rel.
__device__ __forceinline__ float fexp(float x) {
    float y = fmaxf(x * 1.4426950408889634f, -120.f);
    float t = y + 12582912.f;
    int   ki = __float_as_int(t) - 0x4b400000;
    float f = y - (t - 12582912.f);
    float p = 1.3333558146e-3f;
    p = fmaf(p, f, 9.6181291071e-3f);
    p = fmaf(p, f, 5.5504108664e-2f);
    p = fmaf(p, f, 2.4022650695e-1f);
    p = fmaf(p, f, 6.9314718056e-1f);
    p = fmaf(p, f, 1.0f);
    return __int_as_float(__float_as_int(p) + (ki << 23));
}

// ---------------------------------------------------------------------------
// Split pass: fp32 [n] -> fp16 hi[n] + lo[n]
// ---------------------------------------------------------------------------
__global__ void split_f32(const float* __restrict__ src,
                          __half* __restrict__ hi,
                          __half* __restrict__ lo, long long n)
{
    long long i = ((long long)blockIdx.x * blockDim.x + threadIdx.x) * 8;
    if (i >= n) return;
    float4 v0 = *(const float4*)(src + i);
    float4 v1 = *(const float4*)(src + i + 4);
    float f[8] = {v0.x, v0.y, v0.z, v0.w, v1.x, v1.y, v1.z, v1.w};
    uint32_t H[4], L[4];
#pragma unroll
    for (int j = 0; j < 4; j++)
        split_pack(f[2 * j], f[2 * j + 1], H[j], L[j]);
    *(uint4*)(hi + i) = make_uint4(H[0], H[1], H[2], H[3]);
    *(uint4*)(lo + i) = make_uint4(L[0], L[1], L[2], L[3]);
}

// ---------------------------------------------------------------------------
// HMMA GEMM (NT), fp16 2-term, BK=64, 2-stage cp.async pipeline.
// smem/stage: 3 tiles (Ah,Al,Bh) of 128 rows x 128B, xor swizzle. 96 KB total.
// If outH != null: epilogue writes fp16 hi/lo; else fp32 C (+bias).
// ---------------------------------------------------------------------------
#define TB 16384
#define STG (3 * TB)     // 48 KB per stage

__global__ __launch_bounds__(256, 2)
void gemm_split(const __half* __restrict__ Ah,
                const __half* __restrict__ Al,
                const __half* __restrict__ Bh,
                const float* __restrict__ bias, float* __restrict__ C,
                __half* __restrict__ outH, __half* __restrict__ outL,
                int M, int N, int K)
{
    extern __shared__ char sm[];
    const uint32_t sb = smem_u32(sm);

    const int tid  = threadIdx.x;
    const int lane = tid & 31;
    const int wid  = tid >> 5;
    const int wm   = wid & 3;
    const int wn   = wid >> 2;
    const long long m0 = (long long)blockIdx.y * 128;
    const int n0 = blockIdx.x * 128;

    float acc[2][8][4];
#pragma unroll
    for (int i = 0; i < 2; i++)
#pragma unroll
        for (int j = 0; j < 8; j++)
#pragma unroll
            for (int l = 0; l < 4; l++) acc[i][j][l] = 0.f;

    const int arow0 = wm * 32 + (lane & 7) + ((lane >> 3) & 1) * 8;
    const int ac    = lane >> 4;
    const int brow0 = wn * 64 + (lane & 7) + (lane >> 4) * 8;
    const int bc    = (lane >> 3) & 1;

    const int frow = tid >> 3;
    const int fc   = tid & 7;

    const int NCH = K >> 6;

    auto fill = [&](int ch, int st) {
        const uint32_t so = sb + st * STG;
#pragma unroll
        for (int i = 0; i < 4; i++) {
            int row = frow + i * 32;
            uint32_t off = (uint32_t)(row * 128 + ((fc ^ (row & 7)) << 4));
            long long ga = (m0 + row) * K + ch * 64 + fc * 8;
            long long gb = (long long)(n0 + row) * K + ch * 64 + fc * 8;
            cp16(so + off,          Ah + ga);
            cp16(so + TB + off,     Al + ga);
            cp16(so + 2 * TB + off, Bh + gb);
        }
        CP_COMMIT();
    };

    fill(0, 0);

    for (int ch = 0; ch < NCH; ch++) {
        const int st = ch & 1;
        if (ch + 1 < NCH) {
            fill(ch + 1, st ^ 1);
            CP_WAIT(1);
        } else {
            CP_WAIT(0);
        }
        __syncthreads();

        const uint32_t so = sb + st * STG;
#pragma unroll
        for (int kk = 0; kk < 4; kk++) {
            uint32_t ah[2][4], al[2][4];
#pragma unroll
            for (int mt = 0; mt < 2; mt++) {
                int r = arow0 + mt * 16;
                uint32_t off = (uint32_t)(r * 128 + (((2 * kk + ac) ^ (r & 7)) << 4));
                ldsm4(so + off, ah[mt]);
                ldsm4(so + TB + off, al[mt]);
            }
#pragma unroll
            for (int nt = 0; nt < 4; nt++) {
                int r = brow0 + nt * 16;
                uint32_t off = (uint32_t)(r * 128 + (((2 * kk + bc) ^ (r & 7)) << 4));
                uint32_t bh[4];
                ldsm4(so + 2 * TB + off, bh);
#pragma unroll
                for (int mt = 0; mt < 2; mt++) {
                    mma16816(acc[mt][nt * 2],     ah[mt], bh[0], bh[1]);
                    mma16816(acc[mt][nt * 2 + 1], ah[mt], bh[2], bh[3]);
                    mma16816(acc[mt][nt * 2],     al[mt], bh[0], bh[1]);
                    mma16816(acc[mt][nt * 2 + 1], al[mt], bh[2], bh[3]);
                }
            }
        }
        __syncthreads();     // all reads of stage st done before it refills
    }

    const int erow = lane >> 2;
    const int ecol = (lane & 3) * 2;
    if (outH) {
        // fp16 hi/lo epilogue (QKV path; numerically == split(fp32 acc))
#pragma unroll
        for (int mt = 0; mt < 2; mt++) {
#pragma unroll
            for (int nt8 = 0; nt8 < 8; nt8++) {
                long long row = m0 + wm * 32 + mt * 16 + erow;
                int col = n0 + wn * 64 + nt8 * 8 + ecol;
                uint32_t H, L;
                split_pack(acc[mt][nt8][0], acc[mt][nt8][1], H, L);
                *(uint32_t*)(outH + row * N + col) = H;
                *(uint32_t*)(outL + row * N + col) = L;
                split_pack(acc[mt][nt8][2], acc[mt][nt8][3], H, L);
                *(uint32_t*)(outH + (row + 8) * N + col) = H;
                *(uint32_t*)(outL + (row + 8) * N + col) = L;
            }
        }
    } else {
#pragma unroll
        for (int mt = 0; mt < 2; mt++) {
#pragma unroll
            for (int nt8 = 0; nt8 < 8; nt8++) {
                long long row = m0 + wm * 32 + mt * 16 + erow;
                int col = n0 + wn * 64 + nt8 * 8 + ecol;
                float b0 = bias ? bias[col]     : 0.f;
                float b1 = bias ? bias[col + 1] : 0.f;
                float2 r0 = make_float2(acc[mt][nt8][0] + b0, acc[mt][nt8][1] + b1);
                float2 r1 = make_float2(acc[mt][nt8][2] + b0, acc[mt][nt8][3] + b1);
                *(float2*)(C + row * N + col)       = r0;
                *(float2*)(C + (row + 8) * N + col) = r1;
            }
        }
    }
}

// ---------------------------------------------------------------------------
// Tensorized windowed attention, fp16 2-term. Inputs are preSPLIT fp16 hi/lo:
// Qh/Ql/Kh tiles filled by cp.async; V hi transposed by hand (no conversion).
// ---------------------------------------------------------------------------
#define ATB 8192

__global__ __launch_bounds__(128, 4)
void attn_mma(const __half* __restrict__ qh, const __half* __restrict__ ql,
              __half* __restrict__ oh, __half* __restrict__ ol)
{
    extern __shared__ char sm[];
    const uint32_t sb = smem_u32(sm);
    char* Vh = sm + 3 * ATB;

    const int tid  = threadIdx.x;
    const int lane = tid & 31;
    const int wq   = tid >> 5;
    const int h    = blockIdx.x;
    const int wb   = blockIdx.y;

    const long long base = (long long)wb * WINW * QKV_DIM + h * HD;

    // ---- fill Qh, Ql, Kh via cp.async; V hi via manual transpose ----
#pragma unroll
    for (int i = 0; i < 4; i++) {
        int idx = tid + i * 128;          // (row, chunk-of-8-halves)
        int row = idx >> 3;
        int c   = idx & 7;
        long long g = base + (long long)row * QKV_DIM + c * 8;
        uint32_t off = (uint32_t)(row * 128 + ((c ^ (row & 7)) << 4));
        cp16(sb + off,            qh + g);          // Q hi
        cp16(sb + ATB + off,      ql + g);          // Q lo
        cp16(sb + 2 * ATB + off,  qh + g + 512);    // K hi
        // V hi: transpose into Vt[hd][token]
        uint4 v = *(const uint4*)(qh + g + 1024);
        const uint32_t vv[4] = {v.x, v.y, v.z, v.w};
        int tok = row;
#pragma unroll
        for (int e = 0; e < 4; e++) {
            int hd0 = c * 8 + 2 * e;
            uint32_t t0 = (uint32_t)(hd0 * 128 +
                          (((tok >> 3) ^ (hd0 & 7)) << 4) + (tok & 7) * 2);
            int hd1 = hd0 + 1;
            uint32_t t1 = (uint32_t)(hd1 * 128 +
                          (((tok >> 3) ^ (hd1 & 7)) << 4) + (tok & 7) * 2);
            *(uint16_t*)(Vh + t0) = (uint16_t)(vv[e] & 0xffff);
            *(uint16_t*)(Vh + t1) = (uint16_t)(vv[e] >> 16);
        }
    }
    CP_COMMIT();
    CP_WAIT(0);
    __syncthreads();

    const int arow = wq * 16 + (lane & 7) + ((lane >> 3) & 1) * 8;
    const int ac   = lane >> 4;
    const int brow = (lane & 7) + (lane >> 4) * 8;
    const int bc   = (lane >> 3) & 1;

    // ---- S = (Qh+Ql) Kh^T ----
    float s[8][4];
#pragma unroll
    for (int j = 0; j < 8; j++)
#pragma unroll
        for (int l = 0; l < 4; l++) s[j][l] = 0.f;

#pragma unroll
    for (int kk = 0; kk < 4; kk++) {
        uint32_t ah[4], al[4];
        {
            int r = arow;
            uint32_t off = (uint32_t)(r * 128 + (((2 * kk + ac) ^ (r & 7)) << 4));
            ldsm4(sb + off, ah);
            ldsm4(sb + ATB + off, al);
        }
#pragma unroll
        for (int nt = 0; nt < 4; nt++) {
            int r = brow + nt * 16;
            uint32_t off = (uint32_t)(r * 128 + (((2 * kk + bc) ^ (r & 7)) << 4));
            uint32_t bh[4];
            ldsm4(sb + 2 * ATB + off, bh);
            mma16816(s[nt * 2],     ah, bh[0], bh[1]);
            mma16816(s[nt * 2 + 1], ah, bh[2], bh[3]);
            mma16816(s[nt * 2],     al, bh[0], bh[1]);
            mma16816(s[nt * 2 + 1], al, bh[2], bh[3]);
        }
    }

    // ---- softmax in registers ----
    float mx0 = -1e30f, mx1 = -1e30f;
#pragma unroll
    for (int j = 0; j < 8; j++) {
        mx0 = fmaxf(mx0, fmaxf(s[j][0], s[j][1]));
        mx1 = fmaxf(mx1, fmaxf(s[j][2], s[j][3]));
    }
    mx0 = fmaxf(mx0, __shfl_xor_sync(0xffffffffu, mx0, 1));
    mx0 = fmaxf(mx0, __shfl_xor_sync(0xffffffffu, mx0, 2));
    mx1 = fmaxf(mx1, __shfl_xor_sync(0xffffffffu, mx1, 1));
    mx1 = fmaxf(mx1, __shfl_xor_sync(0xffffffffu, mx1, 2));

    float sum0 = 0.f, sum1 = 0.f;
#pragma unroll
    for (int j = 0; j < 8; j++) {
        s[j][0] = fexp(0.125f * (s[j][0] - mx0));
        s[j][1] = fexp(0.125f * (s[j][1] - mx0));
        s[j][2] = fexp(0.125f * (s[j][2] - mx1));
        s[j][3] = fexp(0.125f * (s[j][3] - mx1));
        sum0 += s[j][0] + s[j][1];
        sum1 += s[j][2] + s[j][3];
    }
    sum0 += __shfl_xor_sync(0xffffffffu, sum0, 1);
    sum0 += __shfl_xor_sync(0xffffffffu, sum0, 2);
    sum1 += __shfl_xor_sync(0xffffffffu, sum1, 1);
    sum1 += __shfl_xor_sync(0xffffffffu, sum1, 2);
    const float inv0 = 1.0f / sum0;
    const float inv1 = 1.0f / sum1;

    // ---- O = (Ph+Pl) Vh ----
    float o[8][4];
#pragma unroll
    for (int j = 0; j < 8; j++)
#pragma unroll
        for (int l = 0; l < 4; l++) o[j][l] = 0.f;

#pragma unroll
    for (int j = 0; j < 4; j++) {
        uint32_t ph[4], pl[4];
        split_pack(s[2 * j][0],     s[2 * j][1],     ph[0], pl[0]);
        split_pack(s[2 * j][2],     s[2 * j][3],     ph[1], pl[1]);
        split_pack(s[2 * j + 1][0], s[2 * j + 1][1], ph[2], pl[2]);
        split_pack(s[2 * j + 1][2], s[2 * j + 1][3], ph[3], pl[3]);
#pragma unroll
        for (int nt = 0; nt < 4; nt++) {
            int r = brow + nt * 16;
            uint32_t off = (uint32_t)(r * 128 + (((2 * j + bc) ^ (r & 7)) << 4));
            uint32_t bh[4];
            ldsm4(sb + 3 * ATB + off, bh);
            mma16816(o[nt * 2],     ph, bh[0], bh[1]);
            mma16816(o[nt * 2 + 1], ph, bh[2], bh[3]);
            mma16816(o[nt * 2],     pl, bh[0], bh[1]);
            mma16816(o[nt * 2 + 1], pl, bh[2], bh[3]);
        }
    }

    // ---- epilogue: normalize, split, store fp16 hi/lo ----
    const long long row0 = (long long)wb * WINW + wq * 16 + (lane >> 2);
    const int colb = h * HD + (lane & 3) * 2;
#pragma unroll
    for (int j = 0; j < 8; j++) {
        int col = colb + j * 8;
        uint32_t H, L;
        split_pack(o[j][0] * inv0, o[j][1] * inv0, H, L);
        *(uint32_t*)(oh + row0 * C_DIM + col) = H;
        *(uint32_t*)(ol + row0 * C_DIM + col) = L;
        split_pack(o[j][2] * inv1, o[j][3] * inv1, H, L);
        *(uint32_t*)(oh + (row0 + 8) * C_DIM + col) = H;
        *(uint32_t*)(ol + (row0 + 8) * C_DIM + col) = L;
    }
}

// ---------------------------------------------------------------------------
extern "C" void kernel_launch(void* const* d_in, const int* in_sizes, int n_in,
                              void* d_out, int out_size)
{
    const float* x      = (const float*)d_in[0];
    const float* qkv_w  = (const float*)d_in[1];
    const float* proj_w = (const float*)d_in[2];
    const float* proj_b = (const float*)d_in[3];
    float* out = (float*)d_out;

    __half *qkvh, *qkvl, *xh, *xl, *ath, *atl, *wqh, *wql, *wph, *wpl;
    cudaGetSymbolAddress((void**)&qkvh, g_qkvh);
    cudaGetSymbolAddress((void**)&qkvl, g_qkvl);
    cudaGetSymbolAddress((void**)&xh,  g_xh);
    cudaGetSymbolAddress((void**)&xl,  g_xl);
    cudaGetSymbolAddress((void**)&ath, g_ath);
    cudaGetSymbolAddress((void**)&atl, g_atl);
    cudaGetSymbolAddress((void**)&wqh, g_wqh);
    cudaGetSymbolAddress((void**)&wql, g_wql);
    cudaGetSymbolAddress((void**)&wph, g_wph);
    cudaGetSymbolAddress((void**)&wpl, g_wpl);

    const int gemm_smem = 2 * STG;    // 96 KB (double-buffered)
    const int attn_smem = 4 * ATB;    // 32 KB
    cudaFuncSetAttribute(gemm_split, cudaFuncAttributeMaxDynamicSharedMemorySize,
                         gemm_smem);
    cudaFuncSetAttribute(attn_mma, cudaFuncAttributeMaxDynamicSharedMemorySize,
                         attn_smem);

    // 0) split inputs to fp16 hi/lo
    {
        long long nx = (long long)M_ROWS * C_DIM;
        split_f32<<<(unsigned)((nx / 8 + 255) / 256), 256>>>(x, xh, xl, nx);
        long long nq = (long long)QKV_DIM * C_DIM;
        split_f32<<<(unsigned)((nq / 8 + 255) / 256), 256>>>(qkv_w, wqh, wql, nq);
        long long np = (long long)C_DIM * C_DIM;
        split_f32<<<(unsigned)((np / 8 + 255) / 256), 256>>>(proj_w, wph, wpl, np);
    }

    // 1) QKV projection -> fp16 hi/lo
    gemm_split<<<dim3(QKV_DIM / 128, M_ROWS / 128), 256, gemm_smem>>>(
        xh, xl, wqh, nullptr, nullptr, qkvh, qkvl, M_ROWS, QKV_DIM, C_DIM);

    // 2) Tensorized windowed attention (hi/lo in, hi/lo out)
    attn_mma<<<dim3(NH, NWIN), 128, attn_smem>>>(qkvh, qkvl, ath, atl);

    // 3) Output projection (+bias) -> fp32
    gemm_split<<<dim3(C_DIM / 128, M_ROWS / 128), 256, gemm_smem>>>(
        ath, atl, wph, proj_b, out, nullptr, nullptr, M_ROWS, C_DIM, C_DIM);
}

// round 15
// speedup vs baseline: 1.0001x; 1.0001x over previous
#include <cuda_runtime.h>
#include <cuda_fp16.h>
#include <cstdint>

// ---------------------------------------------------------------------------
// x[65536,512] -> qkv = x @ qkv_w^T -> windowed attn (1024x8, 64x64x64)
//   -> out = att @ proj_w^T + b
// GEMMs: HMMA fp16 2-term split C = (Ah+Al)*Bh, BK=64 SINGLE-buffer smem
// (proven: intra-CTA double buffering regresses; 2 CTA/SM does the overlap).
// QKV GEMM emits fp16 hi/lo; attention consumes hi/lo via cp.async.
// ---------------------------------------------------------------------------

#define M_ROWS   65536
#define C_DIM    512
#define QKV_DIM  1536
#define NH       8
#define HD       64
#define WINW     64
#define NWIN     1024

__device__ __half g_qkvh[(long long)M_ROWS * QKV_DIM];  // qkv hi (fp16)
__device__ __half g_qkvl[(long long)M_ROWS * QKV_DIM];  // qkv lo (fp16)
__device__ __half g_xh [(long long)M_ROWS * C_DIM];
__device__ __half g_xl [(long long)M_ROWS * C_DIM];
__device__ __half g_ath[(long long)M_ROWS * C_DIM];
__device__ __half g_atl[(long long)M_ROWS * C_DIM];
__device__ __half g_wqh[QKV_DIM * C_DIM];
__device__ __half g_wql[QKV_DIM * C_DIM];
__device__ __half g_wph[C_DIM * C_DIM];
__device__ __half g_wpl[C_DIM * C_DIM];

// ------------------------------ helpers ------------------------------------
__device__ __forceinline__ uint32_t smem_u32(const void* p) {
    uint32_t a;
    asm("{ .reg .u64 t; cvta.to.shared.u64 t, %1; cvt.u32.u64 %0, t; }"
        : "=r"(a) : "l"(p));
    return a;
}
__device__ __forceinline__ void ldsm4(uint32_t addr, uint32_t r[4]) {
    asm volatile("ldmatrix.sync.aligned.m8n8.x4.shared.b16 {%0,%1,%2,%3}, [%4];"
                 : "=r"(r[0]), "=r"(r[1]), "=r"(r[2]), "=r"(r[3]) : "r"(addr));
}
__device__ __forceinline__ void mma16816(float d[4], const uint32_t a[4],
                                         const uint32_t b0, const uint32_t b1) {
    asm volatile(
        "mma.sync.aligned.m16n8k16.row.col.f32.f16.f16.f32 "
        "{%0,%1,%2,%3},{%4,%5,%6,%7},{%8,%9},{%0,%1,%2,%3};"
        : "+f"(d[0]), "+f"(d[1]), "+f"(d[2]), "+f"(d[3])
        : "r"(a[0]), "r"(a[1]), "r"(a[2]), "r"(a[3]), "r"(b0), "r"(b1));
}
__device__ __forceinline__ void cp16(uint32_t saddr, const void* gaddr) {
    asm volatile("cp.async.cg.shared.global [%0], [%1], 16;"
                 :: "r"(saddr), "l"(gaddr));
}
#define CP_COMMIT() asm volatile("cp.async.commit_group;" ::: "memory")
#define CP_WAIT0()  asm volatile("cp.async.wait_group 0;" ::: "memory")

__device__ __forceinline__ uint32_t pack2(__half a, __half b) {
    return ((uint32_t)__half_as_ushort(b) << 16) | __half_as_ushort(a);
}
__device__ __forceinline__ void split1(float v, __half& h, __half& l) {
    h = __float2half_rn(v);
    l = __float2half_rn(v - __half2float(h));
}
__device__ __forceinline__ void split_pack(float x, float y,
                                           uint32_t& hh, uint32_t& ll) {
    __half h0, l0, h1, l1;
    split1(x, h0, l0);
    split1(y, h1, l1);
    hh = pack2(h0, h1);
    ll = pack2(l0, l1);
}

// Fast e^x on the FMA pipe (x <= 0). |err| ~ 1e-7 rel.
__device__ __forceinline__ float fexp(float x) {
    float y = fmaxf(x * 1.4426950408889634f, -120.f);
    float t = y + 12582912.f;
    int   ki = __float_as_int(t) - 0x4b400000;
    float f = y - (t - 12582912.f);
    float p = 1.3333558146e-3f;
    p = fmaf(p, f, 9.6181291071e-3f);
    p = fmaf(p, f, 5.5504108664e-2f);
    p = fmaf(p, f, 2.4022650695e-1f);
    p = fmaf(p, f, 6.9314718056e-1f);
    p = fmaf(p, f, 1.0f);
    return __int_as_float(__float_as_int(p) + (ki << 23));
}

// ---------------------------------------------------------------------------
// Split pass: fp32 [n] -> fp16 hi[n] + lo[n]
// ---------------------------------------------------------------------------
__global__ void split_f32(const float* __restrict__ src,
                          __half* __restrict__ hi,
                          __half* __restrict__ lo, long long n)
{
    long long i = ((long long)blockIdx.x * blockDim.x + threadIdx.x) * 8;
    if (i >= n) return;
    float4 v0 = *(const float4*)(src + i);
    float4 v1 = *(const float4*)(src + i + 4);
    float f[8] = {v0.x, v0.y, v0.z, v0.w, v1.x, v1.y, v1.z, v1.w};
    uint32_t H[4], L[4];
#pragma unroll
    for (int j = 0; j < 4; j++)
        split_pack(f[2 * j], f[2 * j + 1], H[j], L[j]);
    *(uint4*)(hi + i) = make_uint4(H[0], H[1], H[2], H[3]);
    *(uint4*)(lo + i) = make_uint4(L[0], L[1], L[2], L[3]);
}

// ---------------------------------------------------------------------------
// HMMA GEMM (NT), fp16 2-term: C = Ah*Bh + Al*Bh, BK=64, single buffer.
// smem: 3 tiles (Ah,Al,Bh) of 128 rows x 128B, xor swizzle. 48 KB, 2 CTA/SM.
// Epilogue: fp16 hi/lo (outH!=null) or fp32 +bias.
// ---------------------------------------------------------------------------
#define TB 16384

__global__ __launch_bounds__(256, 2)
void gemm_split(const __half* __restrict__ Ah,
                const __half* __restrict__ Al,
                const __half* __restrict__ Bh,
                const float* __restrict__ bias, float* __restrict__ C,
                __half* __restrict__ outH, __half* __restrict__ outL,
                int M, int N, int K)
{
    extern __shared__ char sm[];
    const uint32_t sb = smem_u32(sm);

    const int tid  = threadIdx.x;
    const int lane = tid & 31;
    const int wid  = tid >> 5;
    const int wm   = wid & 3;
    const int wn   = wid >> 2;
    const long long m0 = (long long)blockIdx.y * 128;
    const int n0 = blockIdx.x * 128;

    float acc[2][8][4];
#pragma unroll
    for (int i = 0; i < 2; i++)
#pragma unroll
        for (int j = 0; j < 8; j++)
#pragma unroll
            for (int l = 0; l < 4; l++) acc[i][j][l] = 0.f;

    const int arow0 = wm * 32 + (lane & 7) + ((lane >> 3) & 1) * 8;
    const int ac    = lane >> 4;
    const int brow0 = wn * 64 + (lane & 7) + (lane >> 4) * 8;
    const int bc    = (lane >> 3) & 1;

    const int frow = tid >> 3;
    const int fc   = tid & 7;

    const int NCH = K >> 6;
    for (int ch = 0; ch < NCH; ch++) {
        __syncthreads();
#pragma unroll
        for (int i = 0; i < 4; i++) {
            int row = frow + i * 32;
            uint32_t off = (uint32_t)(row * 128 + ((fc ^ (row & 7)) << 4));
            long long ga = (m0 + row) * K + ch * 64 + fc * 8;
            long long gb = (long long)(n0 + row) * K + ch * 64 + fc * 8;
            cp16(sb + off,          Ah + ga);
            cp16(sb + TB + off,     Al + ga);
            cp16(sb + 2 * TB + off, Bh + gb);
        }
        CP_COMMIT();
        CP_WAIT0();
        __syncthreads();

#pragma unroll
        for (int kk = 0; kk < 4; kk++) {
            uint32_t ah[2][4], al[2][4];
#pragma unroll
            for (int mt = 0; mt < 2; mt++) {
                int r = arow0 + mt * 16;
                uint32_t off = (uint32_t)(r * 128 + (((2 * kk + ac) ^ (r & 7)) << 4));
                ldsm4(sb + off, ah[mt]);
                ldsm4(sb + TB + off, al[mt]);
            }
#pragma unroll
            for (int nt = 0; nt < 4; nt++) {
                int r = brow0 + nt * 16;
                uint32_t off = (uint32_t)(r * 128 + (((2 * kk + bc) ^ (r & 7)) << 4));
                uint32_t bh[4];
                ldsm4(sb + 2 * TB + off, bh);
#pragma unroll
                for (int mt = 0; mt < 2; mt++) {
                    mma16816(acc[mt][nt * 2],     ah[mt], bh[0], bh[1]);
                    mma16816(acc[mt][nt * 2 + 1], ah[mt], bh[2], bh[3]);
                    mma16816(acc[mt][nt * 2],     al[mt], bh[0], bh[1]);
                    mma16816(acc[mt][nt * 2 + 1], al[mt], bh[2], bh[3]);
                }
            }
        }
    }

    const int erow = lane >> 2;
    const int ecol = (lane & 3) * 2;
    if (outH) {
        // fp16 hi/lo epilogue (QKV path; numerically == split(fp32 acc))
#pragma unroll
        for (int mt = 0; mt < 2; mt++) {
#pragma unroll
            for (int nt8 = 0; nt8 < 8; nt8++) {
                long long row = m0 + wm * 32 + mt * 16 + erow;
                int col = n0 + wn * 64 + nt8 * 8 + ecol;
                uint32_t H, L;
                split_pack(acc[mt][nt8][0], acc[mt][nt8][1], H, L);
                *(uint32_t*)(outH + row * N + col) = H;
                *(uint32_t*)(outL + row * N + col) = L;
                split_pack(acc[mt][nt8][2], acc[mt][nt8][3], H, L);
                *(uint32_t*)(outH + (row + 8) * N + col) = H;
                *(uint32_t*)(outL + (row + 8) * N + col) = L;
            }
        }
    } else {
#pragma unroll
        for (int mt = 0; mt < 2; mt++) {
#pragma unroll
            for (int nt8 = 0; nt8 < 8; nt8++) {
                long long row = m0 + wm * 32 + mt * 16 + erow;
                int col = n0 + wn * 64 + nt8 * 8 + ecol;
                float b0 = bias ? bias[col]     : 0.f;
                float b1 = bias ? bias[col + 1] : 0.f;
                float2 r0 = make_float2(acc[mt][nt8][0] + b0, acc[mt][nt8][1] + b1);
                float2 r1 = make_float2(acc[mt][nt8][2] + b0, acc[mt][nt8][3] + b1);
                *(float2*)(C + row * N + col)       = r0;
                *(float2*)(C + (row + 8) * N + col) = r1;
            }
        }
    }
}

// ---------------------------------------------------------------------------
// Tensorized windowed attention, fp16 2-term. Inputs preSPLIT fp16 hi/lo:
// Qh/Ql/Kh via cp.async; V hi transposed by hand (no conversion in-kernel).
// ---------------------------------------------------------------------------
#define ATB 8192

__global__ __launch_bounds__(128, 4)
void attn_mma(const __half* __restrict__ qh, const __half* __restrict__ ql,
              __half* __restrict__ oh, __half* __restrict__ ol)
{
    extern __shared__ char sm[];
    const uint32_t sb = smem_u32(sm);
    char* Vh = sm + 3 * ATB;

    const int tid  = threadIdx.x;
    const int lane = tid & 31;
    const int wq   = tid >> 5;
    const int h    = blockIdx.x;
    const int wb   = blockIdx.y;

    const long long base = (long long)wb * WINW * QKV_DIM + h * HD;

    // ---- fill Qh, Ql, Kh via cp.async; V hi via manual transpose ----
#pragma unroll
    for (int i = 0; i < 4; i++) {
        int idx = tid + i * 128;          // (row, chunk-of-8-halves)
        int row = idx >> 3;
        int c   = idx & 7;
        long long g = base + (long long)row * QKV_DIM + c * 8;
        uint32_t off = (uint32_t)(row * 128 + ((c ^ (row & 7)) << 4));
        cp16(sb + off,            qh + g);          // Q hi
        cp16(sb + ATB + off,      ql + g);          // Q lo
        cp16(sb + 2 * ATB + off,  qh + g + 512);    // K hi
        // V hi: transpose into Vt[hd][token]
        uint4 v = *(const uint4*)(qh + g + 1024);
        const uint32_t vv[4] = {v.x, v.y, v.z, v.w};
        int tok = row;
#pragma unroll
        for (int e = 0; e < 4; e++) {
            int hd0 = c * 8 + 2 * e;
            uint32_t t0 = (uint32_t)(hd0 * 128 +
                          (((tok >> 3) ^ (hd0 & 7)) << 4) + (tok & 7) * 2);
            int hd1 = hd0 + 1;
            uint32_t t1 = (uint32_t)(hd1 * 128 +
                          (((tok >> 3) ^ (hd1 & 7)) << 4) + (tok & 7) * 2);
            *(uint16_t*)(Vh + t0) = (uint16_t)(vv[e] & 0xffff);
            *(uint16_t*)(Vh + t1) = (uint16_t)(vv[e] >> 16);
        }
    }
    CP_COMMIT();
    CP_WAIT0();
    __syncthreads();

    const int arow = wq * 16 + (lane & 7) + ((lane >> 3) & 1) * 8;
    const int ac   = lane >> 4;
    const int brow = (lane & 7) + (lane >> 4) * 8;
    const int bc   = (lane >> 3) & 1;

    // ---- S = (Qh+Ql) Kh^T ----
    float s[8][4];
#pragma unroll
    for (int j = 0; j < 8; j++)
#pragma unroll
        for (int l = 0; l < 4; l++) s[j][l] = 0.f;

#pragma unroll
    for (int kk = 0; kk < 4; kk++) {
        uint32_t ah[4], al[4];
        {
            int r = arow;
            uint32_t off = (uint32_t)(r * 128 + (((2 * kk + ac) ^ (r & 7)) << 4));
            ldsm4(sb + off, ah);
            ldsm4(sb + ATB + off, al);
        }
#pragma unroll
        for (int nt = 0; nt < 4; nt++) {
            int r = brow + nt * 16;
            uint32_t off = (uint32_t)(r * 128 + (((2 * kk + bc) ^ (r & 7)) << 4));
            uint32_t bh[4];
            ldsm4(sb + 2 * ATB + off, bh);
            mma16816(s[nt * 2],     ah, bh[0], bh[1]);
            mma16816(s[nt * 2 + 1], ah, bh[2], bh[3]);
            mma16816(s[nt * 2],     al, bh[0], bh[1]);
            mma16816(s[nt * 2 + 1], al, bh[2], bh[3]);
        }
    }

    // ---- softmax in registers ----
    float mx0 = -1e30f, mx1 = -1e30f;
#pragma unroll
    for (int j = 0; j < 8; j++) {
        mx0 = fmaxf(mx0, fmaxf(s[j][0], s[j][1]));
        mx1 = fmaxf(mx1, fmaxf(s[j][2], s[j][3]));
    }
    mx0 = fmaxf(mx0, __shfl_xor_sync(0xffffffffu, mx0, 1));
    mx0 = fmaxf(mx0, __shfl_xor_sync(0xffffffffu, mx0, 2));
    mx1 = fmaxf(mx1, __shfl_xor_sync(0xffffffffu, mx1, 1));
    mx1 = fmaxf(mx1, __shfl_xor_sync(0xffffffffu, mx1, 2));

    float sum0 = 0.f, sum1 = 0.f;
#pragma unroll
    for (int j = 0; j < 8; j++) {
        s[j][0] = fexp(0.125f * (s[j][0] - mx0));
        s[j][1] = fexp(0.125f * (s[j][1] - mx0));
        s[j][2] = fexp(0.125f * (s[j][2] - mx1));
        s[j][3] = fexp(0.125f * (s[j][3] - mx1));
        sum0 += s[j][0] + s[j][1];
        sum1 += s[j][2] + s[j][3];
    }
    sum0 += __shfl_xor_sync(0xffffffffu, sum0, 1);
    sum0 += __shfl_xor_sync(0xffffffffu, sum0, 2);
    sum1 += __shfl_xor_sync(0xffffffffu, sum1, 1);
    sum1 += __shfl_xor_sync(0xffffffffu, sum1, 2);
    const float inv0 = 1.0f / sum0;
    const float inv1 = 1.0f / sum1;

    // ---- O = (Ph+Pl) Vh ----
    float o[8][4];
#pragma unroll
    for (int j = 0; j < 8; j++)
#pragma unroll
        for (int l = 0; l < 4; l++) o[j][l] = 0.f;

#pragma unroll
    for (int j = 0; j < 4; j++) {
        uint32_t ph[4], pl[4];
        split_pack(s[2 * j][0],     s[2 * j][1],     ph[0], pl[0]);
        split_pack(s[2 * j][2],     s[2 * j][3],     ph[1], pl[1]);
        split_pack(s[2 * j + 1][0], s[2 * j + 1][1], ph[2], pl[2]);
        split_pack(s[2 * j + 1][2], s[2 * j + 1][3], ph[3], pl[3]);
#pragma unroll
        for (int nt = 0; nt < 4; nt++) {
            int r = brow + nt * 16;
            uint32_t off = (uint32_t)(r * 128 + (((2 * j + bc) ^ (r & 7)) << 4));
            uint32_t bh[4];
            ldsm4(sb + 3 * ATB + off, bh);
            mma16816(o[nt * 2],     ph, bh[0], bh[1]);
            mma16816(o[nt * 2 + 1], ph, bh[2], bh[3]);
            mma16816(o[nt * 2],     pl, bh[0], bh[1]);
            mma16816(o[nt * 2 + 1], pl, bh[2], bh[3]);
        }
    }

    // ---- epilogue: normalize, split, store fp16 hi/lo ----
    const long long row0 = (long long)wb * WINW + wq * 16 + (lane >> 2);
    const int colb = h * HD + (lane & 3) * 2;
#pragma unroll
    for (int j = 0; j < 8; j++) {
        int col = colb + j * 8;
        uint32_t H, L;
        split_pack(o[j][0] * inv0, o[j][1] * inv0, H, L);
        *(uint32_t*)(oh + row0 * C_DIM + col) = H;
        *(uint32_t*)(ol + row0 * C_DIM + col) = L;
        split_pack(o[j][2] * inv1, o[j][3] * inv1, H, L);
        *(uint32_t*)(oh + (row0 + 8) * C_DIM + col) = H;
        *(uint32_t*)(ol + (row0 + 8) * C_DIM + col) = L;
    }
}

// ---------------------------------------------------------------------------
extern "C" void kernel_launch(void* const* d_in, const int* in_sizes, int n_in,
                              void* d_out, int out_size)
{
    const float* x      = (const float*)d_in[0];
    const float* qkv_w  = (const float*)d_in[1];
    const float* proj_w = (const float*)d_in[2];
    const float* proj_b = (const float*)d_in[3];
    float* out = (float*)d_out;

    __half *qkvh, *qkvl, *xh, *xl, *ath, *atl, *wqh, *wql, *wph, *wpl;
    cudaGetSymbolAddress((void**)&qkvh, g_qkvh);
    cudaGetSymbolAddress((void**)&qkvl, g_qkvl);
    cudaGetSymbolAddress((void**)&xh,  g_xh);
    cudaGetSymbolAddress((void**)&xl,  g_xl);
    cudaGetSymbolAddress((void**)&ath, g_ath);
    cudaGetSymbolAddress((void**)&atl, g_atl);
    cudaGetSymbolAddress((void**)&wqh, g_wqh);
    cudaGetSymbolAddress((void**)&wql, g_wql);
    cudaGetSymbolAddress((void**)&wph, g_wph);
    cudaGetSymbolAddress((void**)&wpl, g_wpl);

    const int gemm_smem = 3 * TB;     // 48 KB (single buffer, 2 CTA/SM)
    const int attn_smem = 4 * ATB;    // 32 KB
    cudaFuncSetAttribute(gemm_split, cudaFuncAttributeMaxDynamicSharedMemorySize,
                         gemm_smem);
    cudaFuncSetAttribute(attn_mma, cudaFuncAttributeMaxDynamicSharedMemorySize,
                         attn_smem);

    // 0) split inputs to fp16 hi/lo
    {
        long long nx = (long long)M_ROWS * C_DIM;
        split_f32<<<(unsigned)((nx / 8 + 255) / 256), 256>>>(x, xh, xl, nx);
        long long nq = (long long)QKV_DIM * C_DIM;
        split_f32<<<(unsigned)((nq / 8 + 255) / 256), 256>>>(qkv_w, wqh, wql, nq);
        long long np = (long long)C_DIM * C_DIM;
        split_f32<<<(unsigned)((np / 8 + 255) / 256), 256>>>(proj_w, wph, wpl, np);
    }

    // 1) QKV projection -> fp16 hi/lo
    gemm_split<<<dim3(QKV_DIM / 128, M_ROWS / 128), 256, gemm_smem>>>(
        xh, xl, wqh, nullptr, nullptr, qkvh, qkvl, M_ROWS, QKV_DIM, C_DIM);

    // 2) Tensorized windowed attention (hi/lo in, hi/lo out)
    attn_mma<<<dim3(NH, NWIN), 128, attn_smem>>>(qkvh, qkvl, ath, atl);

    // 3) Output projection (+bias) -> fp32
    gemm_split<<<dim3(C_DIM / 128, M_ROWS / 128), 256, gemm_smem>>>(
        ath, atl, wph, proj_b, out, nullptr, nullptr, M_ROWS, C_DIM, C_DIM);
}

// round 16
// speedup vs baseline: 1.0647x; 1.0645x over previous
#include <cuda_runtime.h>
#include <cuda_fp16.h>
#include <cstdint>

// ---------------------------------------------------------------------------
// x[65536,512] -> qkv = x @ qkv_w^T -> windowed attn (1024x8, 64x64x64)
//   -> out = att @ proj_w^T + b
// GEMMs: HMMA fp16 2-term split C = (Ah+Al)*Bh, BK=64 single-buffer smem,
// 2 CTA/SM overlap. QKV epilogue emits fp16 hi/lo STAGED THROUGH SMEM for
// full-sector coalesced stores (4B-scatter stores were a 64us regression).
// ---------------------------------------------------------------------------

#define M_ROWS   65536
#define C_DIM    512
#define QKV_DIM  1536
#define NH       8
#define HD       64
#define WINW     64
#define NWIN     1024

__device__ __half g_qkvh[(long long)M_ROWS * QKV_DIM];  // qkv hi (fp16)
__device__ __half g_qkvl[(long long)M_ROWS * QKV_DIM];  // qkv lo (fp16)
__device__ __half g_xh [(long long)M_ROWS * C_DIM];
__device__ __half g_xl [(long long)M_ROWS * C_DIM];
__device__ __half g_ath[(long long)M_ROWS * C_DIM];
__device__ __half g_atl[(long long)M_ROWS * C_DIM];
__device__ __half g_wqh[QKV_DIM * C_DIM];
__device__ __half g_wql[QKV_DIM * C_DIM];
__device__ __half g_wph[C_DIM * C_DIM];
__device__ __half g_wpl[C_DIM * C_DIM];

// ------------------------------ helpers ------------------------------------
__device__ __forceinline__ uint32_t smem_u32(const void* p) {
    uint32_t a;
    asm("{ .reg .u64 t; cvta.to.shared.u64 t, %1; cvt.u32.u64 %0, t; }"
        : "=r"(a) : "l"(p));
    return a;
}
__device__ __forceinline__ void ldsm4(uint32_t addr, uint32_t r[4]) {
    asm volatile("ldmatrix.sync.aligned.m8n8.x4.shared.b16 {%0,%1,%2,%3}, [%4];"
                 : "=r"(r[0]), "=r"(r[1]), "=r"(r[2]), "=r"(r[3]) : "r"(addr));
}
__device__ __forceinline__ void mma16816(float d[4], const uint32_t a[4],
                                         const uint32_t b0, const uint32_t b1) {
    asm volatile(
        "mma.sync.aligned.m16n8k16.row.col.f32.f16.f16.f32 "
        "{%0,%1,%2,%3},{%4,%5,%6,%7},{%8,%9},{%0,%1,%2,%3};"
        : "+f"(d[0]), "+f"(d[1]), "+f"(d[2]), "+f"(d[3])
        : "r"(a[0]), "r"(a[1]), "r"(a[2]), "r"(a[3]), "r"(b0), "r"(b1));
}
__device__ __forceinline__ void cp16(uint32_t saddr, const void* gaddr) {
    asm volatile("cp.async.cg.shared.global [%0], [%1], 16;"
                 :: "r"(saddr), "l"(gaddr));
}
#define CP_COMMIT() asm volatile("cp.async.commit_group;" ::: "memory")
#define CP_WAIT0()  asm volatile("cp.async.wait_group 0;" ::: "memory")

__device__ __forceinline__ uint32_t pack2(__half a, __half b) {
    return ((uint32_t)__half_as_ushort(b) << 16) | __half_as_ushort(a);
}
__device__ __forceinline__ void split1(float v, __half& h, __half& l) {
    h = __float2half_rn(v);
    l = __float2half_rn(v - __half2float(h));
}
__device__ __forceinline__ void split_pack(float x, float y,
                                           uint32_t& hh, uint32_t& ll) {
    __half h0, l0, h1, l1;
    split1(x, h0, l0);
    split1(y, h1, l1);
    hh = pack2(h0, h1);
    ll = pack2(l0, l1);
}

// Fast e^x on the FMA pipe (x <= 0). |err| ~ 1e-7 rel.
__device__ __forceinline__ float fexp(float x) {
    float y = fmaxf(x * 1.4426950408889634f, -120.f);
    float t = y + 12582912.f;
    int   ki = __float_as_int(t) - 0x4b400000;
    float f = y - (t - 12582912.f);
    float p = 1.3333558146e-3f;
    p = fmaf(p, f, 9.6181291071e-3f);
    p = fmaf(p, f, 5.5504108664e-2f);
    p = fmaf(p, f, 2.4022650695e-1f);
    p = fmaf(p, f, 6.9314718056e-1f);
    p = fmaf(p, f, 1.0f);
    return __int_as_float(__float_as_int(p) + (ki << 23));
}

// ---------------------------------------------------------------------------
// Split pass: fp32 [n] -> fp16 hi[n] + lo[n]
// ---------------------------------------------------------------------------
__global__ void split_f32(const float* __restrict__ src,
                          __half* __restrict__ hi,
                          __half* __restrict__ lo, long long n)
{
    long long i = ((long long)blockIdx.x * blockDim.x + threadIdx.x) * 8;
    if (i >= n) return;
    float4 v0 = *(const float4*)(src + i);
    float4 v1 = *(const float4*)(src + i + 4);
    float f[8] = {v0.x, v0.y, v0.z, v0.w, v1.x, v1.y, v1.z, v1.w};
    uint32_t H[4], L[4];
#pragma unroll
    for (int j = 0; j < 4; j++)
        split_pack(f[2 * j], f[2 * j + 1], H[j], L[j]);
    *(uint4*)(hi + i) = make_uint4(H[0], H[1], H[2], H[3]);
    *(uint4*)(lo + i) = make_uint4(L[0], L[1], L[2], L[3]);
}

// ---------------------------------------------------------------------------
// HMMA GEMM (NT), fp16 2-term: C = Ah*Bh + Al*Bh, BK=64, single buffer.
// smem: 3 tiles (Ah,Al,Bh) of 128 rows x 128B, xor swizzle. 48 KB, 2 CTA/SM.
// Epilogue: fp16 hi/lo via smem staging (outH!=null) or fp32 +bias.
// ---------------------------------------------------------------------------
#define TB 16384
#define EPI_STRIDE 144   // epilogue staging row stride (16B aligned, bank+4/row)

__global__ __launch_bounds__(256, 2)
void gemm_split(const __half* __restrict__ Ah,
                const __half* __restrict__ Al,
                const __half* __restrict__ Bh,
                const float* __restrict__ bias, float* __restrict__ C,
                __half* __restrict__ outH, __half* __restrict__ outL,
                int M, int N, int K)
{
    extern __shared__ char sm[];
    const uint32_t sb = smem_u32(sm);

    const int tid  = threadIdx.x;
    const int lane = tid & 31;
    const int wid  = tid >> 5;
    const int wm   = wid & 3;
    const int wn   = wid >> 2;
    const long long m0 = (long long)blockIdx.y * 128;
    const int n0 = blockIdx.x * 128;

    float acc[2][8][4];
#pragma unroll
    for (int i = 0; i < 2; i++)
#pragma unroll
        for (int j = 0; j < 8; j++)
#pragma unroll
            for (int l = 0; l < 4; l++) acc[i][j][l] = 0.f;

    const int arow0 = wm * 32 + (lane & 7) + ((lane >> 3) & 1) * 8;
    const int ac    = lane >> 4;
    const int brow0 = wn * 64 + (lane & 7) + (lane >> 4) * 8;
    const int bc    = (lane >> 3) & 1;

    const int frow = tid >> 3;
    const int fc   = tid & 7;

    const int NCH = K >> 6;
    for (int ch = 0; ch < NCH; ch++) {
        __syncthreads();
#pragma unroll
        for (int i = 0; i < 4; i++) {
            int row = frow + i * 32;
            uint32_t off = (uint32_t)(row * 128 + ((fc ^ (row & 7)) << 4));
            long long ga = (m0 + row) * K + ch * 64 + fc * 8;
            long long gb = (long long)(n0 + row) * K + ch * 64 + fc * 8;
            cp16(sb + off,          Ah + ga);
            cp16(sb + TB + off,     Al + ga);
            cp16(sb + 2 * TB + off, Bh + gb);
        }
        CP_COMMIT();
        CP_WAIT0();
        __syncthreads();

#pragma unroll
        for (int kk = 0; kk < 4; kk++) {
            uint32_t ah[2][4], al[2][4];
#pragma unroll
            for (int mt = 0; mt < 2; mt++) {
                int r = arow0 + mt * 16;
                uint32_t off = (uint32_t)(r * 128 + (((2 * kk + ac) ^ (r & 7)) << 4));
                ldsm4(sb + off, ah[mt]);
                ldsm4(sb + TB + off, al[mt]);
            }
#pragma unroll
            for (int nt = 0; nt < 4; nt++) {
                int r = brow0 + nt * 16;
                uint32_t off = (uint32_t)(r * 128 + (((2 * kk + bc) ^ (r & 7)) << 4));
                uint32_t bh[4];
                ldsm4(sb + 2 * TB + off, bh);
#pragma unroll
                for (int mt = 0; mt < 2; mt++) {
                    mma16816(acc[mt][nt * 2],     ah[mt], bh[0], bh[1]);
                    mma16816(acc[mt][nt * 2 + 1], ah[mt], bh[2], bh[3]);
                    mma16816(acc[mt][nt * 2],     al[mt], bh[0], bh[1]);
                    mma16816(acc[mt][nt * 2 + 1], al[mt], bh[2], bh[3]);
                }
            }
        }
    }

    const int erow = lane >> 2;
    const int ecol = (lane & 3) * 2;
    if (outH) {
        // fp16 hi/lo epilogue, staged through smem for coalesced STG.128.
        __syncthreads();                    // tile buffer now reusable
        char* wptr = sm + wid * (32 * EPI_STRIDE);   // 4608 B/warp, 36 KB total
#pragma unroll
        for (int pass = 0; pass < 2; pass++) {
            __syncwarp();
#pragma unroll
            for (int mt = 0; mt < 2; mt++) {
#pragma unroll
                for (int nt8 = 0; nt8 < 8; nt8++) {
                    uint32_t H0, L0, H1, L1;
                    split_pack(acc[mt][nt8][0], acc[mt][nt8][1], H0, L0);
                    split_pack(acc[mt][nt8][2], acc[mt][nt8][3], H1, L1);
                    uint32_t v0 = pass ? L0 : H0;
                    uint32_t v1 = pass ? L1 : H1;
                    int colb = (nt8 * 8 + ecol) * 2;
                    *(uint32_t*)(wptr + (mt * 16 + erow) * EPI_STRIDE + colb) = v0;
                    *(uint32_t*)(wptr + (mt * 16 + erow + 8) * EPI_STRIDE + colb) = v1;
                }
            }
            __syncwarp();
            __half* dst = pass ? outL : outH;
#pragma unroll
            for (int it = 0; it < 8; it++) {
                int lr = it * 4 + (lane >> 3);
                uint4 v = *(uint4*)(wptr + lr * EPI_STRIDE + (lane & 7) * 16);
                long long row = m0 + wm * 32 + lr;
                *(uint4*)(dst + row * N + n0 + wn * 64 + (lane & 7) * 8) = v;
            }
        }
    } else {
#pragma unroll
        for (int mt = 0; mt < 2; mt++) {
#pragma unroll
            for (int nt8 = 0; nt8 < 8; nt8++) {
                long long row = m0 + wm * 32 + mt * 16 + erow;
                int col = n0 + wn * 64 + nt8 * 8 + ecol;
                float b0 = bias ? bias[col]     : 0.f;
                float b1 = bias ? bias[col + 1] : 0.f;
                float2 r0 = make_float2(acc[mt][nt8][0] + b0, acc[mt][nt8][1] + b1);
                float2 r1 = make_float2(acc[mt][nt8][2] + b0, acc[mt][nt8][3] + b1);
                *(float2*)(C + row * N + col)       = r0;
                *(float2*)(C + (row + 8) * N + col) = r1;
            }
        }
    }
}

// ---------------------------------------------------------------------------
// Tensorized windowed attention, fp16 2-term. Inputs preSPLIT fp16 hi/lo:
// Qh/Ql/Kh via cp.async; V hi transposed by hand (no conversion in-kernel).
// ---------------------------------------------------------------------------
#define ATB 8192

__global__ __launch_bounds__(128, 4)
void attn_mma(const __half* __restrict__ qh, const __half* __restrict__ ql,
              __half* __restrict__ oh, __half* __restrict__ ol)
{
    extern __shared__ char sm[];
    const uint32_t sb = smem_u32(sm);
    char* Vh = sm + 3 * ATB;

    const int tid  = threadIdx.x;
    const int lane = tid & 31;
    const int wq   = tid >> 5;
    const int h    = blockIdx.x;
    const int wb   = blockIdx.y;

    const long long base = (long long)wb * WINW * QKV_DIM + h * HD;

    // ---- fill Qh, Ql, Kh via cp.async; V hi via manual transpose ----
#pragma unroll
    for (int i = 0; i < 4; i++) {
        int idx = tid + i * 128;          // (row, chunk-of-8-halves)
        int row = idx >> 3;
        int c   = idx & 7;
        long long g = base + (long long)row * QKV_DIM + c * 8;
        uint32_t off = (uint32_t)(row * 128 + ((c ^ (row & 7)) << 4));
        cp16(sb + off,            qh + g);          // Q hi
        cp16(sb + ATB + off,      ql + g);          // Q lo
        cp16(sb + 2 * ATB + off,  qh + g + 512);    // K hi
        // V hi: transpose into Vt[hd][token]
        uint4 v = *(const uint4*)(qh + g + 1024);
        const uint32_t vv[4] = {v.x, v.y, v.z, v.w};
        int tok = row;
#pragma unroll
        for (int e = 0; e < 4; e++) {
            int hd0 = c * 8 + 2 * e;
            uint32_t t0 = (uint32_t)(hd0 * 128 +
                          (((tok >> 3) ^ (hd0 & 7)) << 4) + (tok & 7) * 2);
            int hd1 = hd0 + 1;
            uint32_t t1 = (uint32_t)(hd1 * 128 +
                          (((tok >> 3) ^ (hd1 & 7)) << 4) + (tok & 7) * 2);
            *(uint16_t*)(Vh + t0) = (uint16_t)(vv[e] & 0xffff);
            *(uint16_t*)(Vh + t1) = (uint16_t)(vv[e] >> 16);
        }
    }
    CP_COMMIT();
    CP_WAIT0();
    __syncthreads();

    const int arow = wq * 16 + (lane & 7) + ((lane >> 3) & 1) * 8;
    const int ac   = lane >> 4;
    const int brow = (lane & 7) + (lane >> 4) * 8;
    const int bc   = (lane >> 3) & 1;

    // ---- S = (Qh+Ql) Kh^T ----
    float s[8][4];
#pragma unroll
    for (int j = 0; j < 8; j++)
#pragma unroll
        for (int l = 0; l < 4; l++) s[j][l] = 0.f;

#pragma unroll
    for (int kk = 0; kk < 4; kk++) {
        uint32_t ah[4], al[4];
        {
            int r = arow;
            uint32_t off = (uint32_t)(r * 128 + (((2 * kk + ac) ^ (r & 7)) << 4));
            ldsm4(sb + off, ah);
            ldsm4(sb + ATB + off, al);
        }
#pragma unroll
        for (int nt = 0; nt < 4; nt++) {
            int r = brow + nt * 16;
            uint32_t off = (uint32_t)(r * 128 + (((2 * kk + bc) ^ (r & 7)) << 4));
            uint32_t bh[4];
            ldsm4(sb + 2 * ATB + off, bh);
            mma16816(s[nt * 2],     ah, bh[0], bh[1]);
            mma16816(s[nt * 2 + 1], ah, bh[2], bh[3]);
            mma16816(s[nt * 2],     al, bh[0], bh[1]);
            mma16816(s[nt * 2 + 1], al, bh[2], bh[3]);
        }
    }

    // ---- softmax in registers ----
    float mx0 = -1e30f, mx1 = -1e30f;
#pragma unroll
    for (int j = 0; j < 8; j++) {
        mx0 = fmaxf(mx0, fmaxf(s[j][0], s[j][1]));
        mx1 = fmaxf(mx1, fmaxf(s[j][2], s[j][3]));
    }
    mx0 = fmaxf(mx0, __shfl_xor_sync(0xffffffffu, mx0, 1));
    mx0 = fmaxf(mx0, __shfl_xor_sync(0xffffffffu, mx0, 2));
    mx1 = fmaxf(mx1, __shfl_xor_sync(0xffffffffu, mx1, 1));
    mx1 = fmaxf(mx1, __shfl_xor_sync(0xffffffffu, mx1, 2));

    float sum0 = 0.f, sum1 = 0.f;
#pragma unroll
    for (int j = 0; j < 8; j++) {
        s[j][0] = fexp(0.125f * (s[j][0] - mx0));
        s[j][1] = fexp(0.125f * (s[j][1] - mx0));
        s[j][2] = fexp(0.125f * (s[j][2] - mx1));
        s[j][3] = fexp(0.125f * (s[j][3] - mx1));
        sum0 += s[j][0] + s[j][1];
        sum1 += s[j][2] + s[j][3];
    }
    sum0 += __shfl_xor_sync(0xffffffffu, sum0, 1);
    sum0 += __shfl_xor_sync(0xffffffffu, sum0, 2);
    sum1 += __shfl_xor_sync(0xffffffffu, sum1, 1);
    sum1 += __shfl_xor_sync(0xffffffffu, sum1, 2);
    const float inv0 = 1.0f / sum0;
    const float inv1 = 1.0f / sum1;

    // ---- O = (Ph+Pl) Vh ----
    float o[8][4];
#pragma unroll
    for (int j = 0; j < 8; j++)
#pragma unroll
        for (int l = 0; l < 4; l++) o[j][l] = 0.f;

#pragma unroll
    for (int j = 0; j < 4; j++) {
        uint32_t ph[4], pl[4];
        split_pack(s[2 * j][0],     s[2 * j][1],     ph[0], pl[0]);
        split_pack(s[2 * j][2],     s[2 * j][3],     ph[1], pl[1]);
        split_pack(s[2 * j + 1][0], s[2 * j + 1][1], ph[2], pl[2]);
        split_pack(s[2 * j + 1][2], s[2 * j + 1][3], ph[3], pl[3]);
#pragma unroll
        for (int nt = 0; nt < 4; nt++) {
            int r = brow + nt * 16;
            uint32_t off = (uint32_t)(r * 128 + (((2 * j + bc) ^ (r & 7)) << 4));
            uint32_t bh[4];
            ldsm4(sb + 3 * ATB + off, bh);
            mma16816(o[nt * 2],     ph, bh[0], bh[1]);
            mma16816(o[nt * 2 + 1], ph, bh[2], bh[3]);
            mma16816(o[nt * 2],     pl, bh[0], bh[1]);
            mma16816(o[nt * 2 + 1], pl, bh[2], bh[3]);
        }
    }

    // ---- epilogue: normalize, split, store fp16 hi/lo ----
    const long long row0 = (long long)wb * WINW + wq * 16 + (lane >> 2);
    const int colb = h * HD + (lane & 3) * 2;
#pragma unroll
    for (int j = 0; j < 8; j++) {
        int col = colb + j * 8;
        uint32_t H, L;
        split_pack(o[j][0] * inv0, o[j][1] * inv0, H, L);
        *(uint32_t*)(oh + row0 * C_DIM + col) = H;
        *(uint32_t*)(ol + row0 * C_DIM + col) = L;
        split_pack(o[j][2] * inv1, o[j][3] * inv1, H, L);
        *(uint32_t*)(oh + (row0 + 8) * C_DIM + col) = H;
        *(uint32_t*)(ol + (row0 + 8) * C_DIM + col) = L;
    }
}

// ---------------------------------------------------------------------------
extern "C" void kernel_launch(void* const* d_in, const int* in_sizes, int n_in,
                              void* d_out, int out_size)
{
    const float* x      = (const float*)d_in[0];
    const float* qkv_w  = (const float*)d_in[1];
    const float* proj_w = (const float*)d_in[2];
    const float* proj_b = (const float*)d_in[3];
    float* out = (float*)d_out;

    __half *qkvh, *qkvl, *xh, *xl, *ath, *atl, *wqh, *wql, *wph, *wpl;
    cudaGetSymbolAddress((void**)&qkvh, g_qkvh);
    cudaGetSymbolAddress((void**)&qkvl, g_qkvl);
    cudaGetSymbolAddress((void**)&xh,  g_xh);
    cudaGetSymbolAddress((void**)&xl,  g_xl);
    cudaGetSymbolAddress((void**)&ath, g_ath);
    cudaGetSymbolAddress((void**)&atl, g_atl);
    cudaGetSymbolAddress((void**)&wqh, g_wqh);
    cudaGetSymbolAddress((void**)&wql, g_wql);
    cudaGetSymbolAddress((void**)&wph, g_wph);
    cudaGetSymbolAddress((void**)&wpl, g_wpl);

    const int gemm_smem = 3 * TB;     // 48 KB (single buffer, 2 CTA/SM)
    const int attn_smem = 4 * ATB;    // 32 KB
    cudaFuncSetAttribute(gemm_split, cudaFuncAttributeMaxDynamicSharedMemorySize,
                         gemm_smem);
    cudaFuncSetAttribute(attn_mma, cudaFuncAttributeMaxDynamicSharedMemorySize,
                         attn_smem);

    // 0) split inputs to fp16 hi/lo
    {
        long long nx = (long long)M_ROWS * C_DIM;
        split_f32<<<(unsigned)((nx / 8 + 255) / 256), 256>>>(x, xh, xl, nx);
        long long nq = (long long)QKV_DIM * C_DIM;
        split_f32<<<(unsigned)((nq / 8 + 255) / 256), 256>>>(qkv_w, wqh, wql, nq);
        long long np = (long long)C_DIM * C_DIM;
        split_f32<<<(unsigned)((np / 8 + 255) / 256), 256>>>(proj_w, wph, wpl, np);
    }

    // 1) QKV projection -> fp16 hi/lo (smem-staged coalesced epilogue)
    gemm_split<<<dim3(QKV_DIM / 128, M_ROWS / 128), 256, gemm_smem>>>(
        xh, xl, wqh, nullptr, nullptr, qkvh, qkvl, M_ROWS, QKV_DIM, C_DIM);

    // 2) Tensorized windowed attention (hi/lo in, hi/lo out)
    attn_mma<<<dim3(NH, NWIN), 128, attn_smem>>>(qkvh, qkvl, ath, atl);

    // 3) Output projection (+bias) -> fp32
    gemm_split<<<dim3(C_DIM / 128, M_ROWS / 128), 256, gemm_smem>>>(
        ath, atl, wph, proj_b, out, nullptr, nullptr, M_ROWS, C_DIM, C_DIM);
}

// round 17
// speedup vs baseline: 1.0881x; 1.0220x over previous
#include <cuda_runtime.h>
#include <cuda_fp16.h>
#include <cstdint>

// ---------------------------------------------------------------------------
// x[65536,512] -> qkv = x @ qkv_w^T -> windowed attn (1024x8, 64x64x64)
//   -> out = att @ proj_w^T + b
// GEMMs: HMMA fp16 2-term split C = (Ah+Al)*Bh, BK=64 single-buffer smem,
// 2 CTA/SM overlap, smem-staged coalesced fp16 epilogue.
// R17: QKV lo-plane stored only for Q columns (n0<512; K/V lo never read);
//      three input-split launches fused into one.
// ---------------------------------------------------------------------------

#define M_ROWS   65536
#define C_DIM    512
#define QKV_DIM  1536
#define NH       8
#define HD       64
#define WINW     64
#define NWIN     1024

__device__ __half g_qkvh[(long long)M_ROWS * QKV_DIM];  // qkv hi (fp16)
__device__ __half g_qkvl[(long long)M_ROWS * QKV_DIM];  // qkv lo (Q cols only)
__device__ __half g_xh [(long long)M_ROWS * C_DIM];
__device__ __half g_xl [(long long)M_ROWS * C_DIM];
__device__ __half g_ath[(long long)M_ROWS * C_DIM];
__device__ __half g_atl[(long long)M_ROWS * C_DIM];
__device__ __half g_wqh[QKV_DIM * C_DIM];
__device__ __half g_wql[QKV_DIM * C_DIM];
__device__ __half g_wph[C_DIM * C_DIM];
__device__ __half g_wpl[C_DIM * C_DIM];

// ------------------------------ helpers ------------------------------------
__device__ __forceinline__ uint32_t smem_u32(const void* p) {
    uint32_t a;
    asm("{ .reg .u64 t; cvta.to.shared.u64 t, %1; cvt.u32.u64 %0, t; }"
        : "=r"(a) : "l"(p));
    return a;
}
__device__ __forceinline__ void ldsm4(uint32_t addr, uint32_t r[4]) {
    asm volatile("ldmatrix.sync.aligned.m8n8.x4.shared.b16 {%0,%1,%2,%3}, [%4];"
                 : "=r"(r[0]), "=r"(r[1]), "=r"(r[2]), "=r"(r[3]) : "r"(addr));
}
__device__ __forceinline__ void mma16816(float d[4], const uint32_t a[4],
                                         const uint32_t b0, const uint32_t b1) {
    asm volatile(
        "mma.sync.aligned.m16n8k16.row.col.f32.f16.f16.f32 "
        "{%0,%1,%2,%3},{%4,%5,%6,%7},{%8,%9},{%0,%1,%2,%3};"
        : "+f"(d[0]), "+f"(d[1]), "+f"(d[2]), "+f"(d[3])
        : "r"(a[0]), "r"(a[1]), "r"(a[2]), "r"(a[3]), "r"(b0), "r"(b1));
}
__device__ __forceinline__ void cp16(uint32_t saddr, const void* gaddr) {
    asm volatile("cp.async.cg.shared.global [%0], [%1], 16;"
                 :: "r"(saddr), "l"(gaddr));
}
#define CP_COMMIT() asm volatile("cp.async.commit_group;" ::: "memory")
#define CP_WAIT0()  asm volatile("cp.async.wait_group 0;" ::: "memory")

__device__ __forceinline__ uint32_t pack2(__half a, __half b) {
    return ((uint32_t)__half_as_ushort(b) << 16) | __half_as_ushort(a);
}
__device__ __forceinline__ void split1(float v, __half& h, __half& l) {
    h = __float2half_rn(v);
    l = __float2half_rn(v - __half2float(h));
}
__device__ __forceinline__ void split_pack(float x, float y,
                                           uint32_t& hh, uint32_t& ll) {
    __half h0, l0, h1, l1;
    split1(x, h0, l0);
    split1(y, h1, l1);
    hh = pack2(h0, h1);
    ll = pack2(l0, l1);
}

// Fast e^x on the FMA pipe (x <= 0). |err| ~ 1e-7 rel.
__device__ __forceinline__ float fexp(float x) {
    float y = fmaxf(x * 1.4426950408889634f, -120.f);
    float t = y + 12582912.f;
    int   ki = __float_as_int(t) - 0x4b400000;
    float f = y - (t - 12582912.f);
    float p = 1.3333558146e-3f;
    p = fmaf(p, f, 9.6181291071e-3f);
    p = fmaf(p, f, 5.5504108664e-2f);
    p = fmaf(p, f, 2.4022650695e-1f);
    p = fmaf(p, f, 6.9314718056e-1f);
    p = fmaf(p, f, 1.0f);
    return __int_as_float(__float_as_int(p) + (ki << 23));
}

// ---------------------------------------------------------------------------
// Fused split pass: three fp32 arrays -> fp16 hi/lo in one launch.
// Blocks [0, nbx) handle x; next nbq handle qkv_w; last nbp handle proj_w.
// ---------------------------------------------------------------------------
#define SPLIT_TPB 256
__global__ void split_all(const float* __restrict__ x,
                          const float* __restrict__ wq,
                          const float* __restrict__ wp,
                          __half* __restrict__ xh,  __half* __restrict__ xl,
                          __half* __restrict__ wqh, __half* __restrict__ wql,
                          __half* __restrict__ wph, __half* __restrict__ wpl,
                          int nbx, int nbq)
{
    const float* src;
    __half *hi, *lo;
    long long base;
    int b = blockIdx.x;
    if (b < nbx)            { src = x;  hi = xh;  lo = xl;  base = (long long)b * SPLIT_TPB * 8; }
    else if (b < nbx + nbq) { src = wq; hi = wqh; lo = wql; base = (long long)(b - nbx) * SPLIT_TPB * 8; }
    else                    { src = wp; hi = wph; lo = wpl; base = (long long)(b - nbx - nbq) * SPLIT_TPB * 8; }
    long long i = base + (long long)threadIdx.x * 8;
    float4 v0 = *(const float4*)(src + i);
    float4 v1 = *(const float4*)(src + i + 4);
    float f[8] = {v0.x, v0.y, v0.z, v0.w, v1.x, v1.y, v1.z, v1.w};
    uint32_t H[4], L[4];
#pragma unroll
    for (int j = 0; j < 4; j++)
        split_pack(f[2 * j], f[2 * j + 1], H[j], L[j]);
    *(uint4*)(hi + i) = make_uint4(H[0], H[1], H[2], H[3]);
    *(uint4*)(lo + i) = make_uint4(L[0], L[1], L[2], L[3]);
}

// ---------------------------------------------------------------------------
// HMMA GEMM (NT), fp16 2-term: C = Ah*Bh + Al*Bh, BK=64, single buffer.
// smem: 3 tiles (Ah,Al,Bh) of 128 rows x 128B, xor swizzle. 48 KB, 2 CTA/SM.
// Epilogue: fp16 hi/lo via smem staging (outH!=null; lo only if n0<loN)
// or fp32 +bias.
// ---------------------------------------------------------------------------
#define TB 16384
#define EPI_STRIDE 144

__global__ __launch_bounds__(256, 2)
void gemm_split(const __half* __restrict__ Ah,
                const __half* __restrict__ Al,
                const __half* __restrict__ Bh,
                const float* __restrict__ bias, float* __restrict__ C,
                __half* __restrict__ outH, __half* __restrict__ outL,
                int M, int N, int K, int loN)
{
    extern __shared__ char sm[];
    const uint32_t sb = smem_u32(sm);

    const int tid  = threadIdx.x;
    const int lane = tid & 31;
    const int wid  = tid >> 5;
    const int wm   = wid & 3;
    const int wn   = wid >> 2;
    const long long m0 = (long long)blockIdx.y * 128;
    const int n0 = blockIdx.x * 128;

    float acc[2][8][4];
#pragma unroll
    for (int i = 0; i < 2; i++)
#pragma unroll
        for (int j = 0; j < 8; j++)
#pragma unroll
            for (int l = 0; l < 4; l++) acc[i][j][l] = 0.f;

    const int arow0 = wm * 32 + (lane & 7) + ((lane >> 3) & 1) * 8;
    const int ac    = lane >> 4;
    const int brow0 = wn * 64 + (lane & 7) + (lane >> 4) * 8;
    const int bc    = (lane >> 3) & 1;

    const int frow = tid >> 3;
    const int fc   = tid & 7;

    const int NCH = K >> 6;
    for (int ch = 0; ch < NCH; ch++) {
        __syncthreads();
#pragma unroll
        for (int i = 0; i < 4; i++) {
            int row = frow + i * 32;
            uint32_t off = (uint32_t)(row * 128 + ((fc ^ (row & 7)) << 4));
            long long ga = (m0 + row) * K + ch * 64 + fc * 8;
            long long gb = (long long)(n0 + row) * K + ch * 64 + fc * 8;
            cp16(sb + off,          Ah + ga);
            cp16(sb + TB + off,     Al + ga);
            cp16(sb + 2 * TB + off, Bh + gb);
        }
        CP_COMMIT();
        CP_WAIT0();
        __syncthreads();

#pragma unroll
        for (int kk = 0; kk < 4; kk++) {
            uint32_t ah[2][4], al[2][4];
#pragma unroll
            for (int mt = 0; mt < 2; mt++) {
                int r = arow0 + mt * 16;
                uint32_t off = (uint32_t)(r * 128 + (((2 * kk + ac) ^ (r & 7)) << 4));
                ldsm4(sb + off, ah[mt]);
                ldsm4(sb + TB + off, al[mt]);
            }
#pragma unroll
            for (int nt = 0; nt < 4; nt++) {
                int r = brow0 + nt * 16;
                uint32_t off = (uint32_t)(r * 128 + (((2 * kk + bc) ^ (r & 7)) << 4));
                uint32_t bh[4];
                ldsm4(sb + 2 * TB + off, bh);
#pragma unroll
                for (int mt = 0; mt < 2; mt++) {
                    mma16816(acc[mt][nt * 2],     ah[mt], bh[0], bh[1]);
                    mma16816(acc[mt][nt * 2 + 1], ah[mt], bh[2], bh[3]);
                    mma16816(acc[mt][nt * 2],     al[mt], bh[0], bh[1]);
                    mma16816(acc[mt][nt * 2 + 1], al[mt], bh[2], bh[3]);
                }
            }
        }
    }

    const int erow = lane >> 2;
    const int ecol = (lane & 3) * 2;
    if (outH) {
        // fp16 hi/lo epilogue, staged through smem for coalesced STG.128.
        // lo plane stored only when n0 < loN (K/V lo is never consumed).
        __syncthreads();
        char* wptr = sm + wid * (32 * EPI_STRIDE);
        const int npass = (n0 < loN) ? 2 : 1;
        for (int pass = 0; pass < npass; pass++) {
            __syncwarp();
#pragma unroll
            for (int mt = 0; mt < 2; mt++) {
#pragma unroll
                for (int nt8 = 0; nt8 < 8; nt8++) {
                    uint32_t H0, L0, H1, L1;
                    split_pack(acc[mt][nt8][0], acc[mt][nt8][1], H0, L0);
                    split_pack(acc[mt][nt8][2], acc[mt][nt8][3], H1, L1);
                    uint32_t v0 = pass ? L0 : H0;
                    uint32_t v1 = pass ? L1 : H1;
                    int colb = (nt8 * 8 + ecol) * 2;
                    *(uint32_t*)(wptr + (mt * 16 + erow) * EPI_STRIDE + colb) = v0;
                    *(uint32_t*)(wptr + (mt * 16 + erow + 8) * EPI_STRIDE + colb) = v1;
                }
            }
            __syncwarp();
            __half* dst = pass ? outL : outH;
#pragma unroll
            for (int it = 0; it < 8; it++) {
                int lr = it * 4 + (lane >> 3);
                uint4 v = *(uint4*)(wptr + lr * EPI_STRIDE + (lane & 7) * 16);
                long long row = m0 + wm * 32 + lr;
                *(uint4*)(dst + row * N + n0 + wn * 64 + (lane & 7) * 8) = v;
            }
        }
    } else {
#pragma unroll
        for (int mt = 0; mt < 2; mt++) {
#pragma unroll
            for (int nt8 = 0; nt8 < 8; nt8++) {
                long long row = m0 + wm * 32 + mt * 16 + erow;
                int col = n0 + wn * 64 + nt8 * 8 + ecol;
                float b0 = bias ? bias[col]     : 0.f;
                float b1 = bias ? bias[col + 1] : 0.f;
                float2 r0 = make_float2(acc[mt][nt8][0] + b0, acc[mt][nt8][1] + b1);
                float2 r1 = make_float2(acc[mt][nt8][2] + b0, acc[mt][nt8][3] + b1);
                *(float2*)(C + row * N + col)       = r0;
                *(float2*)(C + (row + 8) * N + col) = r1;
            }
        }
    }
}

// ---------------------------------------------------------------------------
// Tensorized windowed attention, fp16 2-term. Inputs preSPLIT fp16 hi/lo:
// Qh/Ql/Kh via cp.async; V hi transposed by hand (no conversion in-kernel).
// ---------------------------------------------------------------------------
#define ATB 8192

__global__ __launch_bounds__(128, 4)
void attn_mma(const __half* __restrict__ qh, const __half* __restrict__ ql,
              __half* __restrict__ oh, __half* __restrict__ ol)
{
    extern __shared__ char sm[];
    const uint32_t sb = smem_u32(sm);
    char* Vh = sm + 3 * ATB;

    const int tid  = threadIdx.x;
    const int lane = tid & 31;
    const int wq   = tid >> 5;
    const int h    = blockIdx.x;
    const int wb   = blockIdx.y;

    const long long base = (long long)wb * WINW * QKV_DIM + h * HD;

    // ---- fill Qh, Ql, Kh via cp.async; V hi via manual transpose ----
#pragma unroll
    for (int i = 0; i < 4; i++) {
        int idx = tid + i * 128;
        int row = idx >> 3;
        int c   = idx & 7;
        long long g = base + (long long)row * QKV_DIM + c * 8;
        uint32_t off = (uint32_t)(row * 128 + ((c ^ (row & 7)) << 4));
        cp16(sb + off,            qh + g);          // Q hi
        cp16(sb + ATB + off,      ql + g);          // Q lo
        cp16(sb + 2 * ATB + off,  qh + g + 512);    // K hi
        // V hi: transpose into Vt[hd][token]
        uint4 v = *(const uint4*)(qh + g + 1024);
        const uint32_t vv[4] = {v.x, v.y, v.z, v.w};
        int tok = row;
#pragma unroll
        for (int e = 0; e < 4; e++) {
            int hd0 = c * 8 + 2 * e;
            uint32_t t0 = (uint32_t)(hd0 * 128 +
                          (((tok >> 3) ^ (hd0 & 7)) << 4) + (tok & 7) * 2);
            int hd1 = hd0 + 1;
            uint32_t t1 = (uint32_t)(hd1 * 128 +
                          (((tok >> 3) ^ (hd1 & 7)) << 4) + (tok & 7) * 2);
            *(uint16_t*)(Vh + t0) = (uint16_t)(vv[e] & 0xffff);
            *(uint16_t*)(Vh + t1) = (uint16_t)(vv[e] >> 16);
        }
    }
    CP_COMMIT();
    CP_WAIT0();
    __syncthreads();

    const int arow = wq * 16 + (lane & 7) + ((lane >> 3) & 1) * 8;
    const int ac   = lane >> 4;
    const int brow = (lane & 7) + (lane >> 4) * 8;
    const int bc   = (lane >> 3) & 1;

    // ---- S = (Qh+Ql) Kh^T ----
    float s[8][4];
#pragma unroll
    for (int j = 0; j < 8; j++)
#pragma unroll
        for (int l = 0; l < 4; l++) s[j][l] = 0.f;

#pragma unroll
    for (int kk = 0; kk < 4; kk++) {
        uint32_t ah[4], al[4];
        {
            int r = arow;
            uint32_t off = (uint32_t)(r * 128 + (((2 * kk + ac) ^ (r & 7)) << 4));
            ldsm4(sb + off, ah);
            ldsm4(sb + ATB + off, al);
        }
#pragma unroll
        for (int nt = 0; nt < 4; nt++) {
            int r = brow + nt * 16;
            uint32_t off = (uint32_t)(r * 128 + (((2 * kk + bc) ^ (r & 7)) << 4));
            uint32_t bh[4];
            ldsm4(sb + 2 * ATB + off, bh);
            mma16816(s[nt * 2],     ah, bh[0], bh[1]);
            mma16816(s[nt * 2 + 1], ah, bh[2], bh[3]);
            mma16816(s[nt * 2],     al, bh[0], bh[1]);
            mma16816(s[nt * 2 + 1], al, bh[2], bh[3]);
        }
    }

    // ---- softmax in registers ----
    float mx0 = -1e30f, mx1 = -1e30f;
#pragma unroll
    for (int j = 0; j < 8; j++) {
        mx0 = fmaxf(mx0, fmaxf(s[j][0], s[j][1]));
        mx1 = fmaxf(mx1, fmaxf(s[j][2], s[j][3]));
    }
    mx0 = fmaxf(mx0, __shfl_xor_sync(0xffffffffu, mx0, 1));
    mx0 = fmaxf(mx0, __shfl_xor_sync(0xffffffffu, mx0, 2));
    mx1 = fmaxf(mx1, __shfl_xor_sync(0xffffffffu, mx1, 1));
    mx1 = fmaxf(mx1, __shfl_xor_sync(0xffffffffu, mx1, 2));

    float sum0 = 0.f, sum1 = 0.f;
#pragma unroll
    for (int j = 0; j < 8; j++) {
        s[j][0] = fexp(0.125f * (s[j][0] - mx0));
        s[j][1] = fexp(0.125f * (s[j][1] - mx0));
        s[j][2] = fexp(0.125f * (s[j][2] - mx1));
        s[j][3] = fexp(0.125f * (s[j][3] - mx1));
        sum0 += s[j][0] + s[j][1];
        sum1 += s[j][2] + s[j][3];
    }
    sum0 += __shfl_xor_sync(0xffffffffu, sum0, 1);
    sum0 += __shfl_xor_sync(0xffffffffu, sum0, 2);
    sum1 += __shfl_xor_sync(0xffffffffu, sum1, 1);
    sum1 += __shfl_xor_sync(0xffffffffu, sum1, 2);
    const float inv0 = 1.0f / sum0;
    const float inv1 = 1.0f / sum1;

    // ---- O = (Ph+Pl) Vh ----
    float o[8][4];
#pragma unroll
    for (int j = 0; j < 8; j++)
#pragma unroll
        for (int l = 0; l < 4; l++) o[j][l] = 0.f;

#pragma unroll
    for (int j = 0; j < 4; j++) {
        uint32_t ph[4], pl[4];
        split_pack(s[2 * j][0],     s[2 * j][1],     ph[0], pl[0]);
        split_pack(s[2 * j][2],     s[2 * j][3],     ph[1], pl[1]);
        split_pack(s[2 * j + 1][0], s[2 * j + 1][1], ph[2], pl[2]);
        split_pack(s[2 * j + 1][2], s[2 * j + 1][3], ph[3], pl[3]);
#pragma unroll
        for (int nt = 0; nt < 4; nt++) {
            int r = brow + nt * 16;
            uint32_t off = (uint32_t)(r * 128 + (((2 * j + bc) ^ (r & 7)) << 4));
            uint32_t bh[4];
            ldsm4(sb + 3 * ATB + off, bh);
            mma16816(o[nt * 2],     ph, bh[0], bh[1]);
            mma16816(o[nt * 2 + 1], ph, bh[2], bh[3]);
            mma16816(o[nt * 2],     pl, bh[0], bh[1]);
            mma16816(o[nt * 2 + 1], pl, bh[2], bh[3]);
        }
    }

    // ---- epilogue: normalize, split, store fp16 hi/lo ----
    const long long row0 = (long long)wb * WINW + wq * 16 + (lane >> 2);
    const int colb = h * HD + (lane & 3) * 2;
#pragma unroll
    for (int j = 0; j < 8; j++) {
        int col = colb + j * 8;
        uint32_t H, L;
        split_pack(o[j][0] * inv0, o[j][1] * inv0, H, L);
        *(uint32_t*)(oh + row0 * C_DIM + col) = H;
        *(uint32_t*)(ol + row0 * C_DIM + col) = L;
        split_pack(o[j][2] * inv1, o[j][3] * inv1, H, L);
        *(uint32_t*)(oh + (row0 + 8) * C_DIM + col) = H;
        *(uint32_t*)(ol + (row0 + 8) * C_DIM + col) = L;
    }
}

// ---------------------------------------------------------------------------
extern "C" void kernel_launch(void* const* d_in, const int* in_sizes, int n_in,
                              void* d_out, int out_size)
{
    const float* x      = (const float*)d_in[0];
    const float* qkv_w  = (const float*)d_in[1];
    const float* proj_w = (const float*)d_in[2];
    const float* proj_b = (const float*)d_in[3];
    float* out = (float*)d_out;

    __half *qkvh, *qkvl, *xh, *xl, *ath, *atl, *wqh, *wql, *wph, *wpl;
    cudaGetSymbolAddress((void**)&qkvh, g_qkvh);
    cudaGetSymbolAddress((void**)&qkvl, g_qkvl);
    cudaGetSymbolAddress((void**)&xh,  g_xh);
    cudaGetSymbolAddress((void**)&xl,  g_xl);
    cudaGetSymbolAddress((void**)&ath, g_ath);
    cudaGetSymbolAddress((void**)&atl, g_atl);
    cudaGetSymbolAddress((void**)&wqh, g_wqh);
    cudaGetSymbolAddress((void**)&wql, g_wql);
    cudaGetSymbolAddress((void**)&wph, g_wph);
    cudaGetSymbolAddress((void**)&wpl, g_wpl);

    const int gemm_smem = 3 * TB;     // 48 KB (single buffer, 2 CTA/SM)
    const int attn_smem = 4 * ATB;    // 32 KB
    cudaFuncSetAttribute(gemm_split, cudaFuncAttributeMaxDynamicSharedMemorySize,
                         gemm_smem);
    cudaFuncSetAttribute(attn_mma, cudaFuncAttributeMaxDynamicSharedMemorySize,
                         attn_smem);

    // 0) fused split of all three fp32 inputs to fp16 hi/lo
    {
        const int ept = SPLIT_TPB * 8;                      // elems per block
        int nbx = (int)(((long long)M_ROWS * C_DIM) / ept); // 16384
        int nbq = (QKV_DIM * C_DIM) / ept;                  // 384
        int nbp = (C_DIM * C_DIM) / ept;                    // 128
        split_all<<<nbx + nbq + nbp, SPLIT_TPB>>>(
            x, qkv_w, proj_w, xh, xl, wqh, wql, wph, wpl, nbx, nbq);
    }

    // 1) QKV projection -> fp16 hi (all) / lo (Q columns only)
    gemm_split<<<dim3(QKV_DIM / 128, M_ROWS / 128), 256, gemm_smem>>>(
        xh, xl, wqh, nullptr, nullptr, qkvh, qkvl,
        M_ROWS, QKV_DIM, C_DIM, C_DIM /* loN: Q occupies cols [0,512) */);

    // 2) Tensorized windowed attention (hi/lo in, hi/lo out)
    attn_mma<<<dim3(NH, NWIN), 128, attn_smem>>>(qkvh, qkvl, ath, atl);

    // 3) Output projection (+bias) -> fp32
    gemm_split<<<dim3(C_DIM / 128, M_ROWS / 128), 256, gemm_smem>>>(
        ath, atl, wph, proj_b, out, nullptr, nullptr,
        M_ROWS, C_DIM, C_DIM, 0);
}